// round 17
// baseline (speedup 1.0000x reference)
#include <cuda_runtime.h>
#include <cuda_fp16.h>
#include <math.h>
#include <stdint.h>

// Problem constants
#define B_  4
#define T_  2048
#define D_  1024
#define H_  16
#define DH_ 64
#define ROWS_ (B_*T_)              // 8192
#define ELEMS_ ((size_t)ROWS_*D_)  // 8,388,608
#define QKVN_ 3072                 // fused QKV width

// Scratch (device globals — no allocation)
__device__ __half g_xh[ELEMS_];                    // fp16 x            [M][1024]
__device__ __half g_wqkvh[(size_t)QKVN_*D_];       // fp16 [Wq|Wk|Wv]^T [3072][1024]
__device__ __half g_woh[(size_t)D_*D_];            // fp16 Wo^T         [1024][1024]
__device__ __half g_qkvh[(size_t)ROWS_*QKVN_];     // fused QKV fp16    [M][3072]
__device__ __half g_qh[ELEMS_];                    // fp16 Q (roped, *log2e/8) [M][1024]
__device__ __half g_kh[ELEMS_];                    // fp16 K (roped)       [M][1024]
__device__ __half g_vh[ELEMS_];                    // fp16 V^T   [B*H][64 dh][2048 t]
__device__ __half g_ah[ELEMS_];                    // fp16 attn out     [M][1024]

#define QSCALE 0.18033688011112042f   // 0.125 * log2(e) — softmax runs in base-2

// ---------------------------------------------------------------------------
// Helpers
// ---------------------------------------------------------------------------
__device__ __forceinline__ void mma_f16(float c[4],
                                        uint32_t a0, uint32_t a1, uint32_t a2, uint32_t a3,
                                        uint32_t b0, uint32_t b1)
{
    asm volatile(
        "mma.sync.aligned.m16n8k16.row.col.f32.f16.f16.f32 "
        "{%0,%1,%2,%3}, {%4,%5,%6,%7}, {%8,%9}, {%0,%1,%2,%3};"
        : "+f"(c[0]), "+f"(c[1]), "+f"(c[2]), "+f"(c[3])
        : "r"(a0), "r"(a1), "r"(a2), "r"(a3), "r"(b0), "r"(b1));
}
__device__ __forceinline__ void cp16(void* s, const void* g) {
    uint32_t sa = (uint32_t)__cvta_generic_to_shared(s);
    asm volatile("cp.async.cg.shared.global [%0], [%1], 16;" :: "r"(sa), "l"(g));
}
#define CP_COMMIT() asm volatile("cp.async.commit_group;")
#define CP_WAIT(n)  asm volatile("cp.async.wait_group %0;" :: "n"(n))
__device__ __forceinline__ uint32_t ld32(const __half* p) {
    return *reinterpret_cast<const uint32_t*>(p);
}
__device__ __forceinline__ void st_h2(__half* p, float a, float b) {
    __half2 h = __floats2half2_rn(a, b);
    *(uint32_t*)p = *(uint32_t*)&h;
}
__device__ __forceinline__ uint32_t pack_h2(float a, float b) {
    __half2 h = __floats2half2_rn(a, b);
    return *(uint32_t*)&h;
}
__device__ __forceinline__ float ex2(float x) {
    float r;
    asm("ex2.approx.f32 %0, %1;" : "=f"(r) : "f"(x));
    return r;
}

// ---------------------------------------------------------------------------
// Merged prep: blocks [0, 8192) convert x to fp16; [8192, 12288) pack weights.
// ---------------------------------------------------------------------------
__global__ __launch_bounds__(256) void prep_all(const float* __restrict__ x,
                                                const float* __restrict__ Wq,
                                                const float* __restrict__ Wk,
                                                const float* __restrict__ Wv,
                                                const float* __restrict__ Wo,
                                                __half* __restrict__ xh,
                                                __half* __restrict__ wqkv,
                                                __half* __restrict__ wo)
{
    if (blockIdx.x < 8192) {
        int i = blockIdx.x * 256 + threadIdx.x;   // over ELEMS_/4
        float4 v = ((const float4*)x)[i];
        __half2 h0 = __floats2half2_rn(v.x, v.y);
        __half2 h1 = __floats2half2_rn(v.z, v.w);
        *(uint2*)&xh[(size_t)i * 4] = make_uint2(*(uint32_t*)&h0, *(uint32_t*)&h1);
    } else {
        __shared__ float t[32][33];
        int i2 = blockIdx.x - 8192;               // 4096 blocks
        int which = i2 >> 10;
        const float* W = (which == 0) ? Wq : (which == 1) ? Wk : (which == 2) ? Wv : Wo;
        __half* out    = (which == 3) ? wo : wqkv;
        int off        = (which == 3) ? 0 : which * 1024;
        int n0 = (i2 & 31) * 32, k0 = ((i2 >> 5) & 31) * 32;
        int tx = threadIdx.x & 31, ty = threadIdx.x >> 5;   // 32 x 8
        #pragma unroll
        for (int j = 0; j < 4; j++)
            t[ty + 8*j][tx] = W[(size_t)(k0 + ty + 8*j) * D_ + n0 + tx];
        __syncthreads();
        #pragma unroll
        for (int j = 0; j < 4; j++) {
            int n = n0 + ty + 8*j;
            out[(size_t)(off + n) * D_ + k0 + tx] = __float2half_rn(t[tx][ty + 8*j]);
        }
    }
}

// ---------------------------------------------------------------------------
// fp16 tensor-core GEMM: A[M,K] @ B^T (B as [N][K] fp16), fp32 accumulate.
// Block tile 128x128, BK=64, 256 threads (8 warps), warp tile 32x64.
// 3-stage cp.async pipeline, one __syncthreads per iteration.  (R13 config)
// ---------------------------------------------------------------------------
#define GSTRIDE 72
#define GSTAGE_H (128*GSTRIDE*2)           // fp16 count per stage (A+B)
#define GSMEM (3 * GSTAGE_H * 2)           // bytes: 110592

__global__ __launch_bounds__(256) void gemm_h(const __half* __restrict__ A,
                                              const __half* __restrict__ Bw,
                                              void* __restrict__ Cv,
                                              int N, int half_out)
{
    extern __shared__ __half hsm[];

    const int tid  = threadIdx.x;
    const int lane = tid & 31;
    const int warp = tid >> 5;
    const int warp_m = warp & 3;
    const int warp_n = warp >> 2;
    const int grp = lane >> 2;
    const int tq  = lane & 3;

    const int row0 = blockIdx.y * 128;
    const int col0 = blockIdx.x * 128;
    const int K = D_;

    float acc[2][8][4];
    #pragma unroll
    for (int mi = 0; mi < 2; mi++)
        #pragma unroll
        for (int ni = 0; ni < 8; ni++)
            #pragma unroll
            for (int e = 0; e < 4; e++) acc[mi][ni][e] = 0.f;

    auto load_stage = [&](int s, int chunk) {
        __half* As = hsm + s * GSTAGE_H;
        __half* Bs = As + 128 * GSTRIDE;
        const __half* Ag = A + (size_t)row0 * K + (chunk << 6);
        const __half* Bg = Bw + (size_t)col0 * K + (chunk << 6);
        #pragma unroll
        for (int i = 0; i < 4; i++) {
            int idx = tid + i * 256;
            int r = idx >> 3, seg = idx & 7;
            cp16(As + r * GSTRIDE + seg * 8, Ag + (size_t)r * K + seg * 8);
            cp16(Bs + r * GSTRIDE + seg * 8, Bg + (size_t)r * K + seg * 8);
        }
        CP_COMMIT();
    };

    const int NIT = K >> 6;   // 16
    load_stage(0, 0);
    load_stage(1, 1);

    #pragma unroll 1
    for (int it = 0; it < NIT; ++it) {
        if (it + 1 < NIT) { CP_WAIT(1); } else { CP_WAIT(0); }
        __syncthreads();
        if (it + 2 < NIT) load_stage((it + 2) % 3, it + 2);

        const __half* As = hsm + (it % 3) * GSTAGE_H;
        const __half* Bs = As + 128 * GSTRIDE;

        #pragma unroll
        for (int ks = 0; ks < 4; ks++) {
            const int kk = 16 * ks;
            uint32_t bf[8][2];
            #pragma unroll
            for (int ni = 0; ni < 8; ni++) {
                int cb = warp_n * 64 + ni * 8 + grp;
                bf[ni][0] = ld32(Bs + cb * GSTRIDE + kk + 2*tq);
                bf[ni][1] = ld32(Bs + cb * GSTRIDE + kk + 2*tq + 8);
            }
            #pragma unroll
            for (int mi = 0; mi < 2; mi++) {
                int rb = warp_m * 32 + mi * 16;
                uint32_t a0 = ld32(As + (rb + grp)     * GSTRIDE + kk + 2*tq);
                uint32_t a1 = ld32(As + (rb + grp + 8) * GSTRIDE + kk + 2*tq);
                uint32_t a2 = ld32(As + (rb + grp)     * GSTRIDE + kk + 2*tq + 8);
                uint32_t a3 = ld32(As + (rb + grp + 8) * GSTRIDE + kk + 2*tq + 8);
                #pragma unroll
                for (int ni = 0; ni < 8; ni++)
                    mma_f16(acc[mi][ni], a0, a1, a2, a3, bf[ni][0], bf[ni][1]);
            }
        }
    }

    if (half_out) {
        __half* C = (__half*)Cv;
        #pragma unroll
        for (int mi = 0; mi < 2; mi++) {
            int r = row0 + warp_m * 32 + mi * 16 + grp;
            #pragma unroll
            for (int ni = 0; ni < 8; ni++) {
                int c = col0 + warp_n * 64 + ni * 8 + tq * 2;
                st_h2(C + (size_t)r * N + c,       acc[mi][ni][0], acc[mi][ni][1]);
                st_h2(C + (size_t)(r + 8) * N + c, acc[mi][ni][2], acc[mi][ni][3]);
            }
        }
    } else {
        float* C = (float*)Cv;
        #pragma unroll
        for (int mi = 0; mi < 2; mi++) {
            int r = row0 + warp_m * 32 + mi * 16 + grp;
            #pragma unroll
            for (int ni = 0; ni < 8; ni++) {
                int c = col0 + warp_n * 64 + ni * 8 + tq * 2;
                *(float2*)&C[(size_t)r * N + c]       = make_float2(acc[mi][ni][0], acc[mi][ni][1]);
                *(float2*)&C[(size_t)(r + 8) * N + c] = make_float2(acc[mi][ni][2], acc[mi][ni][3]);
            }
        }
    }
}

// ---------------------------------------------------------------------------
// Fused RoPE (Q*log2e/8, K) + V transpose.
// Rope: blocks [0, 2048), 8-wide vectorized (uint4). Vtrans: [2048, 10240).
// ---------------------------------------------------------------------------
__global__ __launch_bounds__(256) void rope_vtrans(const __half* __restrict__ QKV,
                                                   __half* __restrict__ Qh,
                                                   __half* __restrict__ Kh,
                                                   __half* __restrict__ Vh,
                                                   const float* __restrict__ cosp,
                                                   const float* __restrict__ sinp)
{
    if (blockIdx.x < 2048) {
        int idx = blockIdx.x * 256 + threadIdx.x;   // over ROWS_*H_*4
        int i = (idx & 3) * 8;              // 0, 8, 16, 24
        int row = idx >> 2;                 // m*16 + h
        int m = row >> 4, h = row & 15;
        int t = m & (T_ - 1);
        size_t qb = (size_t)m * QKVN_ + h * DH_;
        size_t ob = (size_t)m * D_ + h * DH_;

        float clo[8], slo[8], chi[8], shi[8];
        *(float4*)(clo)     = *(const float4*)&cosp[t * DH_ + i];
        *(float4*)(clo + 4) = *(const float4*)&cosp[t * DH_ + i + 4];
        *(float4*)(slo)     = *(const float4*)&sinp[t * DH_ + i];
        *(float4*)(slo + 4) = *(const float4*)&sinp[t * DH_ + i + 4];
        *(float4*)(chi)     = *(const float4*)&cosp[t * DH_ + i + 32];
        *(float4*)(chi + 4) = *(const float4*)&cosp[t * DH_ + i + 36];
        *(float4*)(shi)     = *(const float4*)&sinp[t * DH_ + i + 32];
        *(float4*)(shi + 4) = *(const float4*)&sinp[t * DH_ + i + 36];

        // Q
        {
            uint4 lo4 = *(const uint4*)&QKV[qb + i];
            uint4 hi4 = *(const uint4*)&QKV[qb + i + 32];
            uint32_t loW[4] = {lo4.x, lo4.y, lo4.z, lo4.w};
            uint32_t hiW[4] = {hi4.x, hi4.y, hi4.z, hi4.w};
            uint32_t oL[4], oH[4];
            #pragma unroll
            for (int j = 0; j < 4; j++) {
                float2 l = __half22float2(*(const __half2*)&loW[j]);
                float2 hh = __half22float2(*(const __half2*)&hiW[j]);
                oL[j] = pack_h2((l.x * clo[2*j]   - hh.x * slo[2*j])   * QSCALE,
                                (l.y * clo[2*j+1] - hh.y * slo[2*j+1]) * QSCALE);
                oH[j] = pack_h2((hh.x * chi[2*j]   + l.x * shi[2*j])   * QSCALE,
                                (hh.y * chi[2*j+1] + l.y * shi[2*j+1]) * QSCALE);
            }
            *(uint4*)&Qh[ob + i]      = make_uint4(oL[0], oL[1], oL[2], oL[3]);
            *(uint4*)&Qh[ob + i + 32] = make_uint4(oH[0], oH[1], oH[2], oH[3]);
        }
        // K
        {
            uint4 lo4 = *(const uint4*)&QKV[qb + 1024 + i];
            uint4 hi4 = *(const uint4*)&QKV[qb + 1024 + i + 32];
            uint32_t loW[4] = {lo4.x, lo4.y, lo4.z, lo4.w};
            uint32_t hiW[4] = {hi4.x, hi4.y, hi4.z, hi4.w};
            uint32_t oL[4], oH[4];
            #pragma unroll
            for (int j = 0; j < 4; j++) {
                float2 l = __half22float2(*(const __half2*)&loW[j]);
                float2 hh = __half22float2(*(const __half2*)&hiW[j]);
                oL[j] = pack_h2(l.x * clo[2*j]   - hh.x * slo[2*j],
                                l.y * clo[2*j+1] - hh.y * slo[2*j+1]);
                oH[j] = pack_h2(hh.x * chi[2*j]   + l.x * shi[2*j],
                                hh.y * chi[2*j+1] + l.y * shi[2*j+1]);
            }
            *(uint4*)&Kh[ob + i]      = make_uint4(oL[0], oL[1], oL[2], oL[3]);
            *(uint4*)&Kh[ob + i + 32] = make_uint4(oH[0], oH[1], oH[2], oH[3]);
        }
    } else {
        __shared__ __half t[32][33];
        int i = blockIdx.x - 2048;          // 64 * 2 * 64 blocks
        int t0 = (i & 63) * 32;
        int d0 = ((i >> 6) & 1) * 32;
        int bh = i >> 7;                    // b*16 + h
        int b = bh >> 4, h = bh & 15;
        int tx = threadIdx.x & 31, ty = threadIdx.x >> 5;   // 32 x 8
        const __half* src = QKV + (size_t)b * T_ * QKVN_ + 2048 + h * DH_;
        #pragma unroll
        for (int j = 0; j < 4; j++)
            t[ty + 8*j][tx] = src[(size_t)(t0 + ty + 8*j) * QKVN_ + d0 + tx];
        __syncthreads();
        __half* dst = Vh + ((size_t)bh * DH_) * T_;
        #pragma unroll
        for (int j = 0; j < 4; j++) {
            int dh = d0 + ty + 8*j;
            dst[(size_t)dh * T_ + t0 + tx] = t[tx][ty + 8*j];
        }
    }
}

// ---------------------------------------------------------------------------
// fp16 tensor-core flash attention (causal, base-2 online softmax).
// 256 threads (8 warps x 16 q-rows). Q tile held in SMEM (frees 16 regs);
// exp results packed back into p (frees 16 more); ballot-guarded rescale
// skip; __launch_bounds__(256,3) targets 3 CTAs/SM (occupancy was the
// measured limiter: 23% occ, tensor pipe 33%).
// ---------------------------------------------------------------------------
#define ASTRIDE 72
#define ATILE_H (64*ASTRIDE*2)             // fp16 per K/V stage
#define AQ_OFF  (3*ATILE_H)                // Q tile offset (halves)
#define ASMEM_BYTES ((3*ATILE_H + 128*ASTRIDE) * 2)   // 73728 B

__global__ __launch_bounds__(256, 3) void attn_h(const __half* __restrict__ Qh,
                                                 const __half* __restrict__ Kh,
                                                 const __half* __restrict__ Vh,
                                                 __half* __restrict__ Oh)
{
    extern __shared__ __half hsm[];

    int b = blockIdx.z, h = blockIdx.y;
    int q0 = (gridDim.x - 1 - blockIdx.x) * 128;
    int tid = threadIdx.x;
    int lane = tid & 31, warp = tid >> 5;
    int grp = lane >> 2, tq = lane & 3;

    const __half* Qg = Qh + (size_t)b * T_ * D_ + h * DH_;
    const __half* Kg = Kh + (size_t)b * T_ * D_ + h * DH_;
    const __half* Vg = Vh + ((size_t)(b * H_ + h) * DH_) * T_;
    __half* Og = Oh + (size_t)b * T_ * D_ + h * DH_;

    const int qw  = q0 + 16 * warp;
    const int r0g = qw + grp;
    const int r1g = qw + grp + 8;
    const int rq0 = 16 * warp + grp;        // block-local Q row

    auto load_tile = [&](int s, int j0) {
        __half* Ks = hsm + s * ATILE_H;
        __half* Vs = Ks + 64 * ASTRIDE;
        #pragma unroll
        for (int i = 0; i < 4; i++) {
            int idx = tid + i * 256;
            int mat = idx >> 9;
            int r   = (idx >> 3) & 63;
            int seg = idx & 7;
            if (mat == 0)
                cp16(Ks + r * ASTRIDE + seg * 8, Kg + (size_t)(j0 + r) * D_ + seg * 8);
            else
                cp16(Vs + r * ASTRIDE + seg * 8, Vg + (size_t)r * T_ + j0 + seg * 8);
        }
        CP_COMMIT();
    };

    // Q tile -> smem (commit group 0), then first two K/V tiles (groups 1,2)
    {
        __half* Qs = hsm + AQ_OFF;
        #pragma unroll
        for (int i = 0; i < 4; i++) {
            int idx = tid + i * 256;        // 1024 segs: 128 rows x 8
            int r = idx >> 3, seg = idx & 7;
            cp16(Qs + r * ASTRIDE + seg * 8, Qg + (size_t)(q0 + r) * D_ + seg * 8);
        }
        CP_COMMIT();
    }
    load_tile(0, 0);
    load_tile(1, 64);

    float oacc[8][4];
    #pragma unroll
    for (int nb = 0; nb < 8; nb++)
        #pragma unroll
        for (int e = 0; e < 4; e++) oacc[nb][e] = 0.f;

    float m0 = -1e30f, m1 = -1e30f, l0 = 0.f, l1 = 0.f;

    const __half* Qs = hsm + AQ_OFF;
    const int nt = q0 / 64 + 2;   // >= 2

    #pragma unroll 1
    for (int t = 0; t < nt; ++t) {
        if (t + 1 < nt) { CP_WAIT(1); } else { CP_WAIT(0); }
        __syncthreads();
        if (t + 2 < nt) load_tile((t + 2) % 3, (t + 2) * 64);

        const int j0 = t * 64;
        const __half* Ks = hsm + (t % 3) * ATILE_H;
        const __half* Vs = Ks + 64 * ASTRIDE;

        if (j0 <= qw + 15) {
            const bool full = (j0 + 63 <= qw);

            float p[8][4];
            #pragma unroll
            for (int nb = 0; nb < 8; nb++)
                #pragma unroll
                for (int e = 0; e < 4; e++) p[nb][e] = 0.f;

            #pragma unroll
            for (int ks = 0; ks < 4; ks++) {
                const int kk = 16 * ks;
                uint32_t a0 = ld32(Qs + (rq0)     * ASTRIDE + kk + 2*tq);
                uint32_t a1 = ld32(Qs + (rq0 + 8) * ASTRIDE + kk + 2*tq);
                uint32_t a2 = ld32(Qs + (rq0)     * ASTRIDE + kk + 2*tq + 8);
                uint32_t a3 = ld32(Qs + (rq0 + 8) * ASTRIDE + kk + 2*tq + 8);
                #pragma unroll
                for (int nb = 0; nb < 8; nb++) {
                    uint32_t b0 = ld32(Ks + (8*nb + grp) * ASTRIDE + kk + 2*tq);
                    uint32_t b1 = ld32(Ks + (8*nb + grp) * ASTRIDE + kk + 2*tq + 8);
                    mma_f16(p[nb], a0, a1, a2, a3, b0, b1);
                }
            }

            float mx0 = -1e30f, mx1 = -1e30f;
            #pragma unroll
            for (int nb = 0; nb < 8; nb++) {
                int c = j0 + 8*nb + 2*tq;
                if (!full) {
                    p[nb][0] = (c     <= r0g) ? p[nb][0] : -1e30f;
                    p[nb][1] = (c + 1 <= r0g) ? p[nb][1] : -1e30f;
                    p[nb][2] = (c     <= r1g) ? p[nb][2] : -1e30f;
                    p[nb][3] = (c + 1 <= r1g) ? p[nb][3] : -1e30f;
                }
                mx0 = fmaxf(mx0, fmaxf(p[nb][0], p[nb][1]));
                mx1 = fmaxf(mx1, fmaxf(p[nb][2], p[nb][3]));
            }
            mx0 = fmaxf(mx0, __shfl_xor_sync(0xffffffffu, mx0, 1));
            mx0 = fmaxf(mx0, __shfl_xor_sync(0xffffffffu, mx0, 2));
            mx1 = fmaxf(mx1, __shfl_xor_sync(0xffffffffu, mx1, 1));
            mx1 = fmaxf(mx1, __shfl_xor_sync(0xffffffffu, mx1, 2));

            float mn0 = fmaxf(m0, mx0), mn1 = fmaxf(m1, mx1);
            // Rescale only if some lane's max moved (bit-exact: skipped => cr==1)
            if (__any_sync(0xffffffffu, (mn0 > m0) || (mn1 > m1))) {
                float cr0 = ex2(m0 - mn0), cr1 = ex2(m1 - mn1);
                m0 = mn0; m1 = mn1;
                l0 *= cr0; l1 *= cr1;
                #pragma unroll
                for (int nb = 0; nb < 8; nb++) {
                    oacc[nb][0] *= cr0; oacc[nb][1] *= cr0;
                    oacc[nb][2] *= cr1; oacc[nb][3] *= cr1;
                }
            }

            // exp -> fp16 packs stored back into p[nb][0..1] (l sums rounded vals)
            #pragma unroll
            for (int nb = 0; nb < 8; nb++) {
                float e0 = ex2(p[nb][0] - m0);
                float e1 = ex2(p[nb][1] - m0);
                float e2 = ex2(p[nb][2] - m1);
                float e3 = ex2(p[nb][3] - m1);
                uint32_t u01 = pack_h2(e0, e1);
                uint32_t u23 = pack_h2(e2, e3);
                float2 f01 = __half22float2(*(const __half2*)&u01);
                float2 f23 = __half22float2(*(const __half2*)&u23);
                l0 += f01.x + f01.y;
                l1 += f23.x + f23.y;
                p[nb][0] = __uint_as_float(u01);
                p[nb][1] = __uint_as_float(u23);
            }

            #pragma unroll
            for (int ks = 0; ks < 4; ks++) {
                uint32_t a0 = __float_as_uint(p[2*ks][0]);
                uint32_t a1 = __float_as_uint(p[2*ks][1]);
                uint32_t a2 = __float_as_uint(p[2*ks + 1][0]);
                uint32_t a3 = __float_as_uint(p[2*ks + 1][1]);
                #pragma unroll
                for (int nb = 0; nb < 8; nb++) {
                    uint32_t b0 = ld32(Vs + (8*nb + grp) * ASTRIDE + 16*ks + 2*tq);
                    uint32_t b1 = ld32(Vs + (8*nb + grp) * ASTRIDE + 16*ks + 2*tq + 8);
                    mma_f16(oacc[nb], a0, a1, a2, a3, b0, b1);
                }
            }
        }
    }

    l0 += __shfl_xor_sync(0xffffffffu, l0, 1);
    l0 += __shfl_xor_sync(0xffffffffu, l0, 2);
    l1 += __shfl_xor_sync(0xffffffffu, l1, 1);
    l1 += __shfl_xor_sync(0xffffffffu, l1, 2);
    float inv0 = 1.f / l0, inv1 = 1.f / l1;

    #pragma unroll
    for (int nb = 0; nb < 8; nb++) {
        int c = 8*nb + 2*tq;
        st_h2(Og + (size_t)r0g * D_ + c, oacc[nb][0] * inv0, oacc[nb][1] * inv0);
        st_h2(Og + (size_t)r1g * D_ + c, oacc[nb][2] * inv1, oacc[nb][3] * inv1);
    }
}

// ---------------------------------------------------------------------------
extern "C" void kernel_launch(void* const* d_in, const int* in_sizes, int n_in,
                              void* d_out, int out_size)
{
    const float* x    = (const float*)d_in[0];
    const float* cosp = (const float*)d_in[1];
    const float* sinp = (const float*)d_in[2];
    const float* Wq   = (const float*)d_in[3];
    const float* Wk   = (const float*)d_in[4];
    const float* Wv   = (const float*)d_in[5];
    const float* Wo   = (const float*)d_in[6];
    float* out = (float*)d_out;

    __half *xh, *wqkvh, *woh, *qkvh, *qh, *kh, *vh, *ah;
    cudaGetSymbolAddress((void**)&xh,    g_xh);
    cudaGetSymbolAddress((void**)&wqkvh, g_wqkvh);
    cudaGetSymbolAddress((void**)&woh,   g_woh);
    cudaGetSymbolAddress((void**)&qkvh,  g_qkvh);
    cudaGetSymbolAddress((void**)&qh,    g_qh);
    cudaGetSymbolAddress((void**)&kh,    g_kh);
    cudaGetSymbolAddress((void**)&vh,    g_vh);
    cudaGetSymbolAddress((void**)&ah,    g_ah);

    cudaFuncSetAttribute(gemm_h, cudaFuncAttributeMaxDynamicSharedMemorySize, GSMEM);
    cudaFuncSetAttribute(attn_h, cudaFuncAttributeMaxDynamicSharedMemorySize, ASMEM_BYTES);

    // Prep: x convert + all 4 weight packs, one launch
    prep_all<<<12288, 256>>>(x, Wq, Wk, Wv, Wo, xh, wqkvh, woh);

    // Fused QKV projection (fp16 out)
    dim3 qgrid(QKVN_ / 128, ROWS_ / 128);   // (24, 64)
    gemm_h<<<qgrid, 256, GSMEM>>>(xh, wqkvh, qkvh, QKVN_, 1);

    // Fused RoPE + V transpose (one launch)
    rope_vtrans<<<10240, 256>>>(qkvh, qh, kh, vh, cosp, sinp);

    // Attention (fp16 HMMA, base-2 softmax, 3 CTAs/SM)
    dim3 agrid(T_ / 128, H_, B_);
    attn_h<<<agrid, 256, ASMEM_BYTES>>>(qh, kh, vh, ah);

    // Output projection (fp32 out)
    dim3 ogrid(D_ / 128, ROWS_ / 128);      // (8, 64)
    gemm_h<<<ogrid, 256, GSMEM>>>(ah, woh, out, D_, 0);
}